// round 14
// baseline (speedup 1.0000x reference)
#include <cuda_runtime.h>
#include <cuda_fp16.h>
#include <cstdint>

#define BB   4
#define NP   8192
#define SP   2048
#define D1   128
#define D2   256
#define CIN  384
#define COUT 256
#define RS   384          // row stride (elems) of transposed fp16 activation buffers
#define BN_EPS 1e-5f

#define BM   128
#define BN   128
#define BKc  32
#define SST  40           // smem row stride in fp16 (80 B, conflict-free for ldmatrix)
#define NSLOT 512         // slot array size; this config uses slots 0..255

#define WTOT   (COUT * CIN + 4 * COUT * COUT)
#define OFF_W1 (COUT * CIN)
#define OFF_W2 (OFF_W1 + 2 * COUT * COUT)
#define CC     (COUT * COUT)

// ---------------- scratch ----------------
__device__ float g_p2t[BB * SP * D2];
__device__ float g_t  [(size_t)BB * COUT * NP];          // fp32 raw GEMM out
__device__ __half g_bt[(size_t)BB * NP * RS];            // trunk / input concat [n][c] fp16
__device__ __half g_by[(size_t)BB * NP * RS];            // block intermediate y fp16
__device__ __half g_w [WTOT];                            // all weights fp16
__device__ float g_psum[COUT * NSLOT];
__device__ float g_psq [COUT * NSLOT];
__device__ int   g_idx[BB * NP * 3];
__device__ float g_w3 [BB * NP * 3];
__device__ float g_na [COUT];
__device__ float g_nb [COUT];

__device__ __forceinline__ uint32_t smem_u32(const void* p) {
    uint32_t a;
    asm("{ .reg .u64 t; cvta.to.shared.u64 t, %1; cvt.u32.u64 %0, t; }" : "=r"(a) : "l"(p));
    return a;
}
__device__ __forceinline__ void mma16816(float* c, const uint32_t* a, const uint32_t* b) {
    asm volatile(
        "mma.sync.aligned.m16n8k16.row.col.f32.f16.f16.f32 "
        "{%0,%1,%2,%3}, {%4,%5,%6,%7}, {%8,%9}, {%0,%1,%2,%3};"
        : "+f"(c[0]), "+f"(c[1]), "+f"(c[2]), "+f"(c[3])
        : "r"(a[0]), "r"(a[1]), "r"(a[2]), "r"(a[3]), "r"(b[0]), "r"(b[1]));
}
__device__ __forceinline__ void ldsm4(uint32_t* r, uint32_t addr) {
    asm volatile("ldmatrix.sync.aligned.m8n8.x4.shared.b16 {%0,%1,%2,%3}, [%4];"
        : "=r"(r[0]), "=r"(r[1]), "=r"(r[2]), "=r"(r[3]) : "r"(addr));
}
__device__ __forceinline__ void cp16(uint32_t daddr, const void* src) {
    asm volatile("cp.async.cg.shared.global [%0], [%1], 16;" :: "r"(daddr), "l"(src));
}

// ---------------- KNN: 1 query/thread, float4-packed smem ----------------
__global__ void __launch_bounds__(128) knn_kernel(const float* __restrict__ xyz1,
                                                  const float* __restrict__ xyz2) {
    __shared__ float4 sp[SP];
    int b = blockIdx.y;
    const float* x2 = xyz2 + (size_t)b * 3 * SP;
    for (int i = threadIdx.x; i < SP; i += 128) {
        float X = x2[i], Y = x2[SP + i], Z = x2[2 * SP + i];
        sp[i] = make_float4(X, Y, Z, X * X + Y * Y + Z * Z);
    }
    __syncthreads();
    int n = blockIdx.x * 128 + threadIdx.x;
    const float* x1 = xyz1 + (size_t)b * 3 * NP;
    float qx = x1[n], qy = x1[NP + n], qz = x1[2 * NP + n];
    float qn = qx * qx + qy * qy + qz * qz;

    float d0 = 3.4e38f, d1 = 3.4e38f, d2v = 3.4e38f;
    int i0 = 0, i1 = 0, i2 = 0;
#pragma unroll 4
    for (int s = 0; s < SP; s++) {
        float4 p = sp[s];
        float dot = qx * p.x + qy * p.y + qz * p.z;
        float d = qn + p.w - 2.0f * dot;
        if (d < d2v) {
            if (d < d1) {
                d2v = d1; i2 = i1;
                if (d < d0) { d1 = d0; i1 = i0; d0 = d; i0 = s; }
                else        { d1 = d;  i1 = s; }
            } else { d2v = d; i2 = s; }
        }
    }
    float r0 = 1.0f / (d0 + 1e-8f);
    float r1 = 1.0f / (d1 + 1e-8f);
    float r2 = 1.0f / (d2v + 1e-8f);
    float inv = 1.0f / (r0 + r1 + r2);
    size_t base = ((size_t)b * NP + n) * 3;
    g_idx[base] = i0; g_idx[base + 1] = i1; g_idx[base + 2] = i2;
    g_w3[base] = r0 * inv; g_w3[base + 1] = r1 * inv; g_w3[base + 2] = r2 * inv;
}

// ---------------- transpose points2 [b][c][s] -> [b][s][c] ----------------
__global__ void transpose_p2_kernel(const float* __restrict__ p2) {
    __shared__ float tile[32][33];
    int b = blockIdx.z;
    int s0 = blockIdx.x * 32, c0 = blockIdx.y * 32;
    int tx = threadIdx.x, ty = threadIdx.y;
#pragma unroll
    for (int j = 0; j < 32; j += 8)
        tile[ty + j][tx] = p2[((size_t)b * D2 + c0 + ty + j) * SP + s0 + tx];
    __syncthreads();
    float* dst = g_p2t + (size_t)b * SP * D2;
#pragma unroll
    for (int j = 0; j < 32; j += 8)
        dst[(size_t)(s0 + ty + j) * D2 + c0 + tx] = tile[tx][ty + j];
}

// ---------------- interp: float4 gathers, 4-channel fp16 stores ----------------
__global__ void __launch_bounds__(256) interp_kernel() {
    __shared__ float sw[32][3];
    __shared__ int   si[32][3];
    int b = blockIdx.y;
    int n0 = blockIdx.x * 32;
    int tid = threadIdx.x;
    if (tid < 96) {
        int q = tid / 3, k = tid % 3;
        size_t base = ((size_t)b * NP + n0 + q) * 3 + k;
        sw[q][k] = g_w3[base];
        si[q][k] = g_idx[base];
    }
    __syncthreads();
    const float* f2 = g_p2t + (size_t)b * SP * D2;
    int c4 = (tid & 63) * 4;
    int qh = tid >> 6;
#pragma unroll 2
    for (int qq = 0; qq < 8; qq++) {
        int q = qh * 8 + qq;
        float w0 = sw[q][0], w1 = sw[q][1], w2 = sw[q][2];
        float4 v0 = *(const float4*)(f2 + (size_t)si[q][0] * D2 + c4);
        float4 v1 = *(const float4*)(f2 + (size_t)si[q][1] * D2 + c4);
        float4 v2 = *(const float4*)(f2 + (size_t)si[q][2] * D2 + c4);
        __half2 h0 = __floats2half2_rn(w0 * v0.x + w1 * v1.x + w2 * v2.x,
                                       w0 * v0.y + w1 * v1.y + w2 * v2.y);
        __half2 h1 = __floats2half2_rn(w0 * v0.z + w1 * v1.z + w2 * v2.z,
                                       w0 * v0.w + w1 * v1.w + w2 * v2.w);
        size_t o = ((size_t)b * NP + n0 + q) * RS + D1 + c4;
        *(uint2*)(g_bt + o) = make_uint2(*(uint32_t*)&h0, *(uint32_t*)&h1);
    }
}

// ---------------- points1 -> concat rows [n][0..127], fp16 ----------------
__global__ void convert_p1_kernel(const float* __restrict__ p1) {
    __shared__ float tile[32][33];
    int b = blockIdx.z;
    int n0 = blockIdx.x * 32, c0 = blockIdx.y * 32;
    int tx = threadIdx.x, ty = threadIdx.y;
#pragma unroll
    for (int j = 0; j < 32; j += 8)
        tile[ty + j][tx] = p1[((size_t)b * D1 + c0 + ty + j) * NP + n0 + tx];
    __syncthreads();
    int u = ty * 32 + tx;
    int n_l = u >> 3, cg = u & 7;
    __half2 h0 = __floats2half2_rn(tile[cg * 4 + 0][n_l], tile[cg * 4 + 1][n_l]);
    __half2 h1 = __floats2half2_rn(tile[cg * 4 + 2][n_l], tile[cg * 4 + 3][n_l]);
    size_t o = ((size_t)b * NP + n0 + n_l) * RS + c0 + cg * 4;
    *(uint2*)(g_bt + o) = make_uint2(*(uint32_t*)&h0, *(uint32_t*)&h1);
}

// ---------------- all weights fp32 -> fp16 ----------------
__global__ void convert_w_all_kernel(const float* __restrict__ fw,
                                     const float* __restrict__ w1,
                                     const float* __restrict__ w2) {
    int i = blockIdx.x * 256 + threadIdx.x;
    if (i >= WTOT) return;
    float v;
    if (i < OFF_W1)      v = fw[i];
    else if (i < OFF_W2) v = w1[i - OFF_W1];
    else                 v = w2[i - OFF_W2];
    g_w[i] = __float2half_rn(v);
}

// ---------------- GEMM: fp16 mma.sync, CTA 128x128, 3-stage cp.async,
// 1 sync/K-tile, fused partial BN stats. ----------------
template <int K>
__global__ void __launch_bounds__(256) gemm_mma_kernel(
    const __half* __restrict__ W, const __half* __restrict__ Bt,
    const float* __restrict__ bias) {
    extern __shared__ __half sm[];
    const int ASZ = BM * SST;                 // fp16 elems
    const int BSZ = BN * SST;
    const uint32_t ASZB = ASZ * 2;
    const uint32_t STGB = (ASZ + BSZ) * 2;    // 20480 B per stage

    int tid = threadIdx.x, lane = tid & 31, wid = tid >> 5;
    int wm = wid & 3, wn = wid >> 2;          // 4(M) x 2(N); warp tile 32M x 64N
    int b = blockIdx.z;
    int n0 = blockIdx.x * BN, m0 = blockIdx.y * BM;
    int r = lane >> 2, qk = lane & 3;

    uint32_t sbase = smem_u32(sm);

    int g8 = lane >> 3, lr = lane & 7;
    uint32_t aoff[2], boff[4];
#pragma unroll
    for (int i = 0; i < 2; i++)
        aoff[i] = ((wm * 32 + i * 16 + (g8 & 1) * 8 + lr) * SST + (g8 >> 1) * 8) * 2;
#pragma unroll
    for (int p = 0; p < 4; p++)
        boff[p] = ((wn * 64 + p * 16 + (g8 >> 1) * 8 + lr) * SST + (g8 & 1) * 8) * 2;

    const __half* bt_b = Bt + (size_t)b * NP * RS;
    int brow = tid >> 2, bc = tid & 3;

    float acc[2][8][4];
#pragma unroll
    for (int i = 0; i < 2; i++)
#pragma unroll
        for (int j = 0; j < 8; j++)
#pragma unroll
            for (int q = 0; q < 4; q++) acc[i][j][q] = 0.f;

    const int NT = K / BKc;

    auto issue = [&](int t) {
        int kc = t * BKc;
        uint32_t st = sbase + (uint32_t)(t % 3) * STGB;
#pragma unroll
        for (int i = 0; i < 2; i++) {        // A: 512 chunks of 16B
            int idx = tid + i * 256;
            int row = idx >> 2, c = idx & 3;
            uint32_t d = st + (uint32_t)(row * SST + c * 8) * 2;
            cp16(d, W + (size_t)(m0 + row) * K + kc + c * 8);
        }
#pragma unroll
        for (int i = 0; i < 2; i++) {        // B: 512 chunks of 16B (128 rows)
            int idx = tid + i * 256;
            int row = idx >> 2, c = idx & 3;
            uint32_t d = st + ASZB + (uint32_t)(row * SST + c * 8) * 2;
            cp16(d, bt_b + (size_t)(n0 + row) * RS + kc + c * 8);
        }
        asm volatile("cp.async.commit_group;" ::: "memory");
    };
    (void)brow; (void)bc;

    issue(0);
    if (NT > 1) issue(1);

    for (int t = 0; t < NT; t++) {
        if (t + 1 < NT) {
            asm volatile("cp.async.wait_group 1;" ::: "memory");
        } else {
            asm volatile("cp.async.wait_group 0;" ::: "memory");
        }
        __syncthreads();
        uint32_t st = sbase + (uint32_t)(t % 3) * STGB;
#pragma unroll
        for (int k16 = 0; k16 < BKc; k16 += 16) {
            uint32_t kb = (uint32_t)k16 * 2;
            uint32_t ah[2][4], bh[4][4];
            ldsm4(ah[0], st + aoff[0] + kb);
            ldsm4(ah[1], st + aoff[1] + kb);
            ldsm4(bh[0], st + ASZB + boff[0] + kb);
            ldsm4(bh[1], st + ASZB + boff[1] + kb);
            ldsm4(bh[2], st + ASZB + boff[2] + kb);
            ldsm4(bh[3], st + ASZB + boff[3] + kb);
#pragma unroll
            for (int i = 0; i < 2; i++)
#pragma unroll
                for (int j = 0; j < 8; j++)
                    mma16816(acc[i][j], ah[i], &bh[j >> 1][(j & 1) * 2]);
        }
        if (t + 2 < NT) issue(t + 2);
    }

    // ---- epilogue: bias add, store fp32 t, partial stats ----
    float* Yb = g_t + (size_t)b * COUT * NP;
    float ssum[4] = {0.f, 0.f, 0.f, 0.f}, ssq[4] = {0.f, 0.f, 0.f, 0.f};
#pragma unroll
    for (int i = 0; i < 2; i++) {
        int m = m0 + wm * 32 + i * 16 + r;
        float bs0 = bias[m], bs8 = bias[m + 8];
#pragma unroll
        for (int j = 0; j < 8; j++) {
            int n = n0 + wn * 64 + j * 8 + qk * 2;
            float v0 = acc[i][j][0] + bs0, v1 = acc[i][j][1] + bs0;
            float v2 = acc[i][j][2] + bs8, v3 = acc[i][j][3] + bs8;
            *(float2*)(Yb + (size_t)m * NP + n)       = make_float2(v0, v1);
            *(float2*)(Yb + (size_t)(m + 8) * NP + n) = make_float2(v2, v3);
            ssum[i * 2]     += v0 + v1;  ssq[i * 2]     += v0 * v0 + v1 * v1;
            ssum[i * 2 + 1] += v2 + v3;  ssq[i * 2 + 1] += v2 * v2 + v3 * v3;
        }
    }
#pragma unroll
    for (int o = 1; o < 4; o <<= 1) {
#pragma unroll
        for (int k = 0; k < 4; k++) {
            ssum[k] += __shfl_xor_sync(0xffffffff, ssum[k], o);
            ssq[k]  += __shfl_xor_sync(0xffffffff, ssq[k], o);
        }
    }
    float* sb = (float*)sm;
    __syncthreads();
    if (qk == 0) {
#pragma unroll
        for (int k = 0; k < 4; k++) {
            int row = wm * 32 + (k >> 1) * 16 + (k & 1) * 8 + r;
            sb[(wn * 128 + row) * 2]     = ssum[k];
            sb[(wn * 128 + row) * 2 + 1] = ssq[k];
        }
    }
    __syncthreads();
    if (tid < 128) {
        float S = sb[tid * 2]     + sb[(128 + tid) * 2];
        float Q = sb[tid * 2 + 1] + sb[(128 + tid) * 2 + 1];
        int slot = blockIdx.x + gridDim.x * blockIdx.z;   // 0..255
        g_psum[(size_t)(m0 + tid) * NSLOT + slot] = S;
        g_psq [(size_t)(m0 + tid) * NSLOT + slot] = Q;
    }
}

// ---------------- finalize BN: 256 slots, one per thread ----------------
__global__ void __launch_bounds__(256) finalize_kernel(const float* __restrict__ gamma,
                                                       const float* __restrict__ beta) {
    int c = blockIdx.x, tid = threadIdx.x;
    float s = g_psum[(size_t)c * NSLOT + tid];
    float q = g_psq [(size_t)c * NSLOT + tid];
    __shared__ float rs[256], rq[256];
    rs[tid] = s; rq[tid] = q;
    __syncthreads();
    for (int o = 128; o > 0; o >>= 1) {
        if (tid < o) { rs[tid] += rs[tid + o]; rq[tid] += rq[tid + o]; }
        __syncthreads();
    }
    if (tid == 0) {
        float inv = 1.0f / (float)(BB * NP);
        float mean = rs[0] * inv;
        float var = rq[0] * inv - mean * mean;
        float a = gamma[c] * rsqrtf(var + BN_EPS);
        g_na[c] = a;
        g_nb[c] = beta[c] - mean * a;
    }
}

// ---------------- BN-apply: tile 64c x 32n, fp16 out, 16B stores ----------
template <bool RES, bool WOUT, bool WBT>
__global__ void applyT_kernel(const __half* __restrict__ Tr,
                              __half* __restrict__ D,
                              float* __restrict__ O) {
    __shared__ float ts[64][33];
    __shared__ float t2[64][33];
    int b = blockIdx.z;
    int n0 = blockIdx.x * 32, c0 = blockIdx.y * 64;
    int tx = threadIdx.x, ty = threadIdx.y;
#pragma unroll
    for (int j = 0; j < 64; j += 8) {
        int c = c0 + ty + j;
        size_t off = ((size_t)b * COUT + c) * NP + n0 + tx;
        ts[ty + j][tx] = fmaf(g_na[c], g_t[off], g_nb[c]);
    }
    __syncthreads();
    {
        int u = ty * 32 + tx;
        int n_l = u >> 3, cg = u & 7;
        size_t o = ((size_t)b * NP + n0 + n_l) * RS + c0 + cg * 8;
        float v[8];
#pragma unroll
        for (int i = 0; i < 8; i++) v[i] = ts[cg * 8 + i][n_l];
        if (RES) {
            uint4 rr = *(const uint4*)(Tr + o);
            const __half* pr = (const __half*)&rr;
#pragma unroll
            for (int i = 0; i < 8; i++) v[i] += __half2float(pr[i]);
        }
#pragma unroll
        for (int i = 0; i < 8; i++) v[i] = fmaxf(v[i], 0.f);
        if (WBT) {
            uint4 ud;
            __half2* pd = (__half2*)&ud;
#pragma unroll
            for (int i = 0; i < 4; i++)
                pd[i] = __floats2half2_rn(v[2 * i], v[2 * i + 1]);
            *(uint4*)(D + o) = ud;
        }
        if (WOUT) {
#pragma unroll
            for (int i = 0; i < 8; i++) t2[cg * 8 + i][n_l] = v[i];
        }
    }
    if (WOUT) {
        __syncthreads();
#pragma unroll
        for (int j = 0; j < 64; j += 8)
            O[((size_t)b * COUT + c0 + ty + j) * NP + n0 + tx] = t2[ty + j][tx];
    }
}

// ---------------- launch ----------------
extern "C" void kernel_launch(void* const* d_in, const int* in_sizes, int n_in,
                              void* d_out, int out_size) {
    const float* xyz1    = (const float*)d_in[0];
    const float* xyz2    = (const float*)d_in[1];
    const float* points1 = (const float*)d_in[2];
    const float* points2 = (const float*)d_in[3];
    const float* fuse_W  = (const float*)d_in[4];
    const float* fuse_b  = (const float*)d_in[5];
    const float* fuse_g  = (const float*)d_in[6];
    const float* fuse_be = (const float*)d_in[7];
    const float* blk_W1  = (const float*)d_in[8];
    const float* blk_b1  = (const float*)d_in[9];
    const float* blk_g1  = (const float*)d_in[10];
    const float* blk_be1 = (const float*)d_in[11];
    const float* blk_W2  = (const float*)d_in[12];
    const float* blk_b2  = (const float*)d_in[13];
    const float* blk_g2  = (const float*)d_in[14];
    const float* blk_be2 = (const float*)d_in[15];
    float* out = (float*)d_out;

    void* pv;
    cudaGetSymbolAddress(&pv, g_w);  __half* w  = (__half*)pv;
    cudaGetSymbolAddress(&pv, g_bt); __half* bt = (__half*)pv;
    cudaGetSymbolAddress(&pv, g_by); __half* by = (__half*)pv;

    const int SMEM_GEMM = 3 * (BM + BN) * SST * 2;     // 61440 B
    cudaFuncSetAttribute(gemm_mma_kernel<CIN>,  cudaFuncAttributeMaxDynamicSharedMemorySize, SMEM_GEMM);
    cudaFuncSetAttribute(gemm_mma_kernel<COUT>, cudaFuncAttributeMaxDynamicSharedMemorySize, SMEM_GEMM);

    dim3 ggrid(NP / BN, COUT / BM, BB);                 // (64, 2, 4)
    dim3 agrid(NP / 32, COUT / 64, BB);                 // (256, 4, 4)
    dim3 ablk(32, 8);

    convert_w_all_kernel<<<(WTOT + 255) / 256, 256>>>(fuse_W, blk_W1, blk_W2);
    transpose_p2_kernel<<<dim3(SP / 32, D2 / 32, BB), ablk>>>(points2);
    knn_kernel<<<dim3(NP / 128, BB), 128>>>(xyz1, xyz2);
    interp_kernel<<<dim3(NP / 32, BB), 256>>>();
    convert_p1_kernel<<<dim3(NP / 32, D1 / 32, BB), ablk>>>(points1);

    // fuse: 384 -> 256, BN, relu -> trunk bt
    gemm_mma_kernel<CIN><<<ggrid, 256, SMEM_GEMM>>>(w, bt, fuse_b);
    finalize_kernel<<<COUT, 256>>>(fuse_g, fuse_be);
    applyT_kernel<false, false, true><<<agrid, ablk>>>(nullptr, bt, nullptr);

    for (int i = 0; i < 2; i++) {
        gemm_mma_kernel<COUT><<<ggrid, 256, SMEM_GEMM>>>(
            w + OFF_W1 + (size_t)i * CC, bt, blk_b1 + (size_t)i * COUT);
        finalize_kernel<<<COUT, 256>>>(blk_g1 + (size_t)i * COUT, blk_be1 + (size_t)i * COUT);
        applyT_kernel<false, false, true><<<agrid, ablk>>>(nullptr, by, nullptr);

        gemm_mma_kernel<COUT><<<ggrid, 256, SMEM_GEMM>>>(
            w + OFF_W2 + (size_t)i * CC, by, blk_b2 + (size_t)i * COUT);
        finalize_kernel<<<COUT, 256>>>(blk_g2 + (size_t)i * COUT, blk_be2 + (size_t)i * COUT);
        if (i == 0)
            applyT_kernel<true, false, true><<<agrid, ablk>>>(bt, bt, nullptr);
        else
            applyT_kernel<true, true, false><<<agrid, ablk>>>(bt, nullptr, out);
    }
}

// round 15
// speedup vs baseline: 1.0139x; 1.0139x over previous
#include <cuda_runtime.h>
#include <cuda_fp16.h>
#include <cstdint>

#define BB   4
#define NP   8192
#define SP   2048
#define D1   128
#define D2   256
#define CIN  384
#define COUT 256
#define RS   384          // row stride (elems) of transposed fp16 activation buffers
#define BN_EPS 1e-5f

#define BM   128
#define BN   128
#define BKc  64
#define SST  72           // smem row stride in fp16 (144 B; stride 36 words ≡ 4 mod 32 → ldmatrix conflict-free)
#define NSLOT 512         // slot array size; this config uses slots 0..255

#define WTOT   (COUT * CIN + 4 * COUT * COUT)
#define OFF_W1 (COUT * CIN)
#define OFF_W2 (OFF_W1 + 2 * COUT * COUT)
#define CC     (COUT * COUT)

// ---------------- scratch ----------------
__device__ float g_p2t[BB * SP * D2];
__device__ float g_t  [(size_t)BB * COUT * NP];          // fp32 raw GEMM out
__device__ __half g_bt[(size_t)BB * NP * RS];            // trunk / input concat [n][c] fp16
__device__ __half g_by[(size_t)BB * NP * RS];            // block intermediate y fp16
__device__ __half g_w [WTOT];                            // all weights fp16
__device__ float g_psum[COUT * NSLOT];
__device__ float g_psq [COUT * NSLOT];
__device__ int   g_idx[BB * NP * 3];
__device__ float g_w3 [BB * NP * 3];
__device__ float g_na [COUT];
__device__ float g_nb [COUT];

__device__ __forceinline__ uint32_t smem_u32(const void* p) {
    uint32_t a;
    asm("{ .reg .u64 t; cvta.to.shared.u64 t, %1; cvt.u32.u64 %0, t; }" : "=r"(a) : "l"(p));
    return a;
}
__device__ __forceinline__ void mma16816(float* c, const uint32_t* a, const uint32_t* b) {
    asm volatile(
        "mma.sync.aligned.m16n8k16.row.col.f32.f16.f16.f32 "
        "{%0,%1,%2,%3}, {%4,%5,%6,%7}, {%8,%9}, {%0,%1,%2,%3};"
        : "+f"(c[0]), "+f"(c[1]), "+f"(c[2]), "+f"(c[3])
        : "r"(a[0]), "r"(a[1]), "r"(a[2]), "r"(a[3]), "r"(b[0]), "r"(b[1]));
}
__device__ __forceinline__ void ldsm4(uint32_t* r, uint32_t addr) {
    asm volatile("ldmatrix.sync.aligned.m8n8.x4.shared.b16 {%0,%1,%2,%3}, [%4];"
        : "=r"(r[0]), "=r"(r[1]), "=r"(r[2]), "=r"(r[3]) : "r"(addr));
}
__device__ __forceinline__ void cp16(uint32_t daddr, const void* src) {
    asm volatile("cp.async.cg.shared.global [%0], [%1], 16;" :: "r"(daddr), "l"(src));
}

// ---------------- KNN: 1 query/thread, float4-packed smem ----------------
__global__ void __launch_bounds__(128) knn_kernel(const float* __restrict__ xyz1,
                                                  const float* __restrict__ xyz2) {
    __shared__ float4 sp[SP];
    int b = blockIdx.y;
    const float* x2 = xyz2 + (size_t)b * 3 * SP;
    for (int i = threadIdx.x; i < SP; i += 128) {
        float X = x2[i], Y = x2[SP + i], Z = x2[2 * SP + i];
        sp[i] = make_float4(X, Y, Z, X * X + Y * Y + Z * Z);
    }
    __syncthreads();
    int n = blockIdx.x * 128 + threadIdx.x;
    const float* x1 = xyz1 + (size_t)b * 3 * NP;
    float qx = x1[n], qy = x1[NP + n], qz = x1[2 * NP + n];
    float qn = qx * qx + qy * qy + qz * qz;

    float d0 = 3.4e38f, d1 = 3.4e38f, d2v = 3.4e38f;
    int i0 = 0, i1 = 0, i2 = 0;
#pragma unroll 4
    for (int s = 0; s < SP; s++) {
        float4 p = sp[s];
        float dot = qx * p.x + qy * p.y + qz * p.z;
        float d = qn + p.w - 2.0f * dot;
        if (d < d2v) {
            if (d < d1) {
                d2v = d1; i2 = i1;
                if (d < d0) { d1 = d0; i1 = i0; d0 = d; i0 = s; }
                else        { d1 = d;  i1 = s; }
            } else { d2v = d; i2 = s; }
        }
    }
    float r0 = 1.0f / (d0 + 1e-8f);
    float r1 = 1.0f / (d1 + 1e-8f);
    float r2 = 1.0f / (d2v + 1e-8f);
    float inv = 1.0f / (r0 + r1 + r2);
    size_t base = ((size_t)b * NP + n) * 3;
    g_idx[base] = i0; g_idx[base + 1] = i1; g_idx[base + 2] = i2;
    g_w3[base] = r0 * inv; g_w3[base + 1] = r1 * inv; g_w3[base + 2] = r2 * inv;
}

// ---------------- transpose points2 [b][c][s] -> [b][s][c] ----------------
__global__ void transpose_p2_kernel(const float* __restrict__ p2) {
    __shared__ float tile[32][33];
    int b = blockIdx.z;
    int s0 = blockIdx.x * 32, c0 = blockIdx.y * 32;
    int tx = threadIdx.x, ty = threadIdx.y;
#pragma unroll
    for (int j = 0; j < 32; j += 8)
        tile[ty + j][tx] = p2[((size_t)b * D2 + c0 + ty + j) * SP + s0 + tx];
    __syncthreads();
    float* dst = g_p2t + (size_t)b * SP * D2;
#pragma unroll
    for (int j = 0; j < 32; j += 8)
        dst[(size_t)(s0 + ty + j) * D2 + c0 + tx] = tile[tx][ty + j];
}

// ---------------- interp: float4 gathers, 4-channel fp16 stores ----------------
__global__ void __launch_bounds__(256) interp_kernel() {
    __shared__ float sw[32][3];
    __shared__ int   si[32][3];
    int b = blockIdx.y;
    int n0 = blockIdx.x * 32;
    int tid = threadIdx.x;
    if (tid < 96) {
        int q = tid / 3, k = tid % 3;
        size_t base = ((size_t)b * NP + n0 + q) * 3 + k;
        sw[q][k] = g_w3[base];
        si[q][k] = g_idx[base];
    }
    __syncthreads();
    const float* f2 = g_p2t + (size_t)b * SP * D2;
    int c4 = (tid & 63) * 4;
    int qh = tid >> 6;
#pragma unroll 2
    for (int qq = 0; qq < 8; qq++) {
        int q = qh * 8 + qq;
        float w0 = sw[q][0], w1 = sw[q][1], w2 = sw[q][2];
        float4 v0 = *(const float4*)(f2 + (size_t)si[q][0] * D2 + c4);
        float4 v1 = *(const float4*)(f2 + (size_t)si[q][1] * D2 + c4);
        float4 v2 = *(const float4*)(f2 + (size_t)si[q][2] * D2 + c4);
        __half2 h0 = __floats2half2_rn(w0 * v0.x + w1 * v1.x + w2 * v2.x,
                                       w0 * v0.y + w1 * v1.y + w2 * v2.y);
        __half2 h1 = __floats2half2_rn(w0 * v0.z + w1 * v1.z + w2 * v2.z,
                                       w0 * v0.w + w1 * v1.w + w2 * v2.w);
        size_t o = ((size_t)b * NP + n0 + q) * RS + D1 + c4;
        *(uint2*)(g_bt + o) = make_uint2(*(uint32_t*)&h0, *(uint32_t*)&h1);
    }
}

// ---------------- points1 -> concat rows [n][0..127], fp16 ----------------
__global__ void convert_p1_kernel(const float* __restrict__ p1) {
    __shared__ float tile[32][33];
    int b = blockIdx.z;
    int n0 = blockIdx.x * 32, c0 = blockIdx.y * 32;
    int tx = threadIdx.x, ty = threadIdx.y;
#pragma unroll
    for (int j = 0; j < 32; j += 8)
        tile[ty + j][tx] = p1[((size_t)b * D1 + c0 + ty + j) * NP + n0 + tx];
    __syncthreads();
    int u = ty * 32 + tx;
    int n_l = u >> 3, cg = u & 7;
    __half2 h0 = __floats2half2_rn(tile[cg * 4 + 0][n_l], tile[cg * 4 + 1][n_l]);
    __half2 h1 = __floats2half2_rn(tile[cg * 4 + 2][n_l], tile[cg * 4 + 3][n_l]);
    size_t o = ((size_t)b * NP + n0 + n_l) * RS + c0 + cg * 4;
    *(uint2*)(g_bt + o) = make_uint2(*(uint32_t*)&h0, *(uint32_t*)&h1);
}

// ---------------- all weights fp32 -> fp16 ----------------
__global__ void convert_w_all_kernel(const float* __restrict__ fw,
                                     const float* __restrict__ w1,
                                     const float* __restrict__ w2) {
    int i = blockIdx.x * 256 + threadIdx.x;
    if (i >= WTOT) return;
    float v;
    if (i < OFF_W1)      v = fw[i];
    else if (i < OFF_W2) v = w1[i - OFF_W1];
    else                 v = w2[i - OFF_W2];
    g_w[i] = __float2half_rn(v);
}

// ---------------- GEMM: fp16 mma.sync, CTA 128x128, BKc=64, 2-stage cp.async,
// 1 sync/K-tile, fused partial BN stats. ----------------
template <int K>
__global__ void __launch_bounds__(256) gemm_mma_kernel(
    const __half* __restrict__ W, const __half* __restrict__ Bt,
    const float* __restrict__ bias) {
    extern __shared__ __half sm[];
    const int ASZ = BM * SST;                 // fp16 elems
    const uint32_t ASZB = ASZ * 2;            // 18432 B
    const uint32_t STGB = 2 * ASZB;           // 36864 B per stage (A + B)

    int tid = threadIdx.x, lane = tid & 31, wid = tid >> 5;
    int wm = wid & 3, wn = wid >> 2;          // 4(M) x 2(N); warp tile 32M x 64N
    int b = blockIdx.z;
    int n0 = blockIdx.x * BN, m0 = blockIdx.y * BM;
    int r = lane >> 2, qk = lane & 3;

    uint32_t sbase = smem_u32(sm);

    int g8 = lane >> 3, lr = lane & 7;
    uint32_t aoff[2], boff[4];
#pragma unroll
    for (int i = 0; i < 2; i++)
        aoff[i] = ((wm * 32 + i * 16 + (g8 & 1) * 8 + lr) * SST + (g8 >> 1) * 8) * 2;
#pragma unroll
    for (int p = 0; p < 4; p++)
        boff[p] = ((wn * 64 + p * 16 + (g8 >> 1) * 8 + lr) * SST + (g8 & 1) * 8) * 2;

    const __half* bt_b = Bt + (size_t)b * NP * RS;

    float acc[2][8][4];
#pragma unroll
    for (int i = 0; i < 2; i++)
#pragma unroll
        for (int j = 0; j < 8; j++)
#pragma unroll
            for (int q = 0; q < 4; q++) acc[i][j][q] = 0.f;

    const int NT = K / BKc;

    auto issue = [&](int t) {
        int kc = t * BKc;
        uint32_t st = sbase + (uint32_t)(t & 1) * STGB;
#pragma unroll
        for (int i = 0; i < 4; i++) {        // A: 1024 chunks of 16B (128 rows x 8)
            int idx = tid + i * 256;
            int row = idx >> 3, c = idx & 7;
            uint32_t d = st + (uint32_t)(row * SST + c * 8) * 2;
            cp16(d, W + (size_t)(m0 + row) * K + kc + c * 8);
        }
#pragma unroll
        for (int i = 0; i < 4; i++) {        // B: 1024 chunks of 16B (128 rows x 8)
            int idx = tid + i * 256;
            int row = idx >> 3, c = idx & 7;
            uint32_t d = st + ASZB + (uint32_t)(row * SST + c * 8) * 2;
            cp16(d, bt_b + (size_t)(n0 + row) * RS + kc + c * 8);
        }
        asm volatile("cp.async.commit_group;" ::: "memory");
    };

    issue(0);

    for (int t = 0; t < NT; t++) {
        asm volatile("cp.async.wait_group 0;" ::: "memory");
        __syncthreads();
        if (t + 1 < NT) issue(t + 1);        // overlaps this tile's compute
        uint32_t st = sbase + (uint32_t)(t & 1) * STGB;
#pragma unroll
        for (int k16 = 0; k16 < BKc; k16 += 16) {
            uint32_t kb = (uint32_t)k16 * 2;
            uint32_t ah[2][4], bh[4][4];
            ldsm4(ah[0], st + aoff[0] + kb);
            ldsm4(ah[1], st + aoff[1] + kb);
            ldsm4(bh[0], st + ASZB + boff[0] + kb);
            ldsm4(bh[1], st + ASZB + boff[1] + kb);
            ldsm4(bh[2], st + ASZB + boff[2] + kb);
            ldsm4(bh[3], st + ASZB + boff[3] + kb);
#pragma unroll
            for (int i = 0; i < 2; i++)
#pragma unroll
                for (int j = 0; j < 8; j++)
                    mma16816(acc[i][j], ah[i], &bh[j >> 1][(j & 1) * 2]);
        }
    }

    // ---- epilogue: bias add, store fp32 t, partial stats ----
    float* Yb = g_t + (size_t)b * COUT * NP;
    float ssum[4] = {0.f, 0.f, 0.f, 0.f}, ssq[4] = {0.f, 0.f, 0.f, 0.f};
#pragma unroll
    for (int i = 0; i < 2; i++) {
        int m = m0 + wm * 32 + i * 16 + r;
        float bs0 = bias[m], bs8 = bias[m + 8];
#pragma unroll
        for (int j = 0; j < 8; j++) {
            int n = n0 + wn * 64 + j * 8 + qk * 2;
            float v0 = acc[i][j][0] + bs0, v1 = acc[i][j][1] + bs0;
            float v2 = acc[i][j][2] + bs8, v3 = acc[i][j][3] + bs8;
            *(float2*)(Yb + (size_t)m * NP + n)       = make_float2(v0, v1);
            *(float2*)(Yb + (size_t)(m + 8) * NP + n) = make_float2(v2, v3);
            ssum[i * 2]     += v0 + v1;  ssq[i * 2]     += v0 * v0 + v1 * v1;
            ssum[i * 2 + 1] += v2 + v3;  ssq[i * 2 + 1] += v2 * v2 + v3 * v3;
        }
    }
#pragma unroll
    for (int o = 1; o < 4; o <<= 1) {
#pragma unroll
        for (int k = 0; k < 4; k++) {
            ssum[k] += __shfl_xor_sync(0xffffffff, ssum[k], o);
            ssq[k]  += __shfl_xor_sync(0xffffffff, ssq[k], o);
        }
    }
    float* sb = (float*)sm;
    __syncthreads();
    if (qk == 0) {
#pragma unroll
        for (int k = 0; k < 4; k++) {
            int row = wm * 32 + (k >> 1) * 16 + (k & 1) * 8 + r;
            sb[(wn * 128 + row) * 2]     = ssum[k];
            sb[(wn * 128 + row) * 2 + 1] = ssq[k];
        }
    }
    __syncthreads();
    if (tid < 128) {
        float S = sb[tid * 2]     + sb[(128 + tid) * 2];
        float Q = sb[tid * 2 + 1] + sb[(128 + tid) * 2 + 1];
        int slot = blockIdx.x + gridDim.x * blockIdx.z;   // 0..255
        g_psum[(size_t)(m0 + tid) * NSLOT + slot] = S;
        g_psq [(size_t)(m0 + tid) * NSLOT + slot] = Q;
    }
}

// ---------------- finalize BN: 256 slots, one per thread ----------------
__global__ void __launch_bounds__(256) finalize_kernel(const float* __restrict__ gamma,
                                                       const float* __restrict__ beta) {
    int c = blockIdx.x, tid = threadIdx.x;
    float s = g_psum[(size_t)c * NSLOT + tid];
    float q = g_psq [(size_t)c * NSLOT + tid];
    __shared__ float rs[256], rq[256];
    rs[tid] = s; rq[tid] = q;
    __syncthreads();
    for (int o = 128; o > 0; o >>= 1) {
        if (tid < o) { rs[tid] += rs[tid + o]; rq[tid] += rq[tid + o]; }
        __syncthreads();
    }
    if (tid == 0) {
        float inv = 1.0f / (float)(BB * NP);
        float mean = rs[0] * inv;
        float var = rq[0] * inv - mean * mean;
        float a = gamma[c] * rsqrtf(var + BN_EPS);
        g_na[c] = a;
        g_nb[c] = beta[c] - mean * a;
    }
}

// ---------------- BN-apply: tile 64c x 32n, fp16 out, 16B stores ----------
template <bool RES, bool WOUT, bool WBT>
__global__ void applyT_kernel(const __half* __restrict__ Tr,
                              __half* __restrict__ D,
                              float* __restrict__ O) {
    __shared__ float ts[64][33];
    __shared__ float t2[64][33];
    int b = blockIdx.z;
    int n0 = blockIdx.x * 32, c0 = blockIdx.y * 64;
    int tx = threadIdx.x, ty = threadIdx.y;
#pragma unroll
    for (int j = 0; j < 64; j += 8) {
        int c = c0 + ty + j;
        size_t off = ((size_t)b * COUT + c) * NP + n0 + tx;
        ts[ty + j][tx] = fmaf(g_na[c], g_t[off], g_nb[c]);
    }
    __syncthreads();
    {
        int u = ty * 32 + tx;
        int n_l = u >> 3, cg = u & 7;
        size_t o = ((size_t)b * NP + n0 + n_l) * RS + c0 + cg * 8;
        float v[8];
#pragma unroll
        for (int i = 0; i < 8; i++) v[i] = ts[cg * 8 + i][n_l];
        if (RES) {
            uint4 rr = *(const uint4*)(Tr + o);
            const __half* pr = (const __half*)&rr;
#pragma unroll
            for (int i = 0; i < 8; i++) v[i] += __half2float(pr[i]);
        }
#pragma unroll
        for (int i = 0; i < 8; i++) v[i] = fmaxf(v[i], 0.f);
        if (WBT) {
            uint4 ud;
            __half2* pd = (__half2*)&ud;
#pragma unroll
            for (int i = 0; i < 4; i++)
                pd[i] = __floats2half2_rn(v[2 * i], v[2 * i + 1]);
            *(uint4*)(D + o) = ud;
        }
        if (WOUT) {
#pragma unroll
            for (int i = 0; i < 8; i++) t2[cg * 8 + i][n_l] = v[i];
        }
    }
    if (WOUT) {
        __syncthreads();
#pragma unroll
        for (int j = 0; j < 64; j += 8)
            O[((size_t)b * COUT + c0 + ty + j) * NP + n0 + tx] = t2[ty + j][tx];
    }
}

// ---------------- launch ----------------
extern "C" void kernel_launch(void* const* d_in, const int* in_sizes, int n_in,
                              void* d_out, int out_size) {
    const float* xyz1    = (const float*)d_in[0];
    const float* xyz2    = (const float*)d_in[1];
    const float* points1 = (const float*)d_in[2];
    const float* points2 = (const float*)d_in[3];
    const float* fuse_W  = (const float*)d_in[4];
    const float* fuse_b  = (const float*)d_in[5];
    const float* fuse_g  = (const float*)d_in[6];
    const float* fuse_be = (const float*)d_in[7];
    const float* blk_W1  = (const float*)d_in[8];
    const float* blk_b1  = (const float*)d_in[9];
    const float* blk_g1  = (const float*)d_in[10];
    const float* blk_be1 = (const float*)d_in[11];
    const float* blk_W2  = (const float*)d_in[12];
    const float* blk_b2  = (const float*)d_in[13];
    const float* blk_g2  = (const float*)d_in[14];
    const float* blk_be2 = (const float*)d_in[15];
    float* out = (float*)d_out;

    void* pv;
    cudaGetSymbolAddress(&pv, g_w);  __half* w  = (__half*)pv;
    cudaGetSymbolAddress(&pv, g_bt); __half* bt = (__half*)pv;
    cudaGetSymbolAddress(&pv, g_by); __half* by = (__half*)pv;

    const int SMEM_GEMM = 2 * 2 * BM * SST * 2;        // 73728 B
    cudaFuncSetAttribute(gemm_mma_kernel<CIN>,  cudaFuncAttributeMaxDynamicSharedMemorySize, SMEM_GEMM);
    cudaFuncSetAttribute(gemm_mma_kernel<COUT>, cudaFuncAttributeMaxDynamicSharedMemorySize, SMEM_GEMM);

    dim3 ggrid(NP / BN, COUT / BM, BB);                 // (64, 2, 4)
    dim3 agrid(NP / 32, COUT / 64, BB);                 // (256, 4, 4)
    dim3 ablk(32, 8);

    convert_w_all_kernel<<<(WTOT + 255) / 256, 256>>>(fuse_W, blk_W1, blk_W2);
    transpose_p2_kernel<<<dim3(SP / 32, D2 / 32, BB), ablk>>>(points2);
    knn_kernel<<<dim3(NP / 128, BB), 128>>>(xyz1, xyz2);
    interp_kernel<<<dim3(NP / 32, BB), 256>>>();
    convert_p1_kernel<<<dim3(NP / 32, D1 / 32, BB), ablk>>>(points1);

    // fuse: 384 -> 256, BN, relu -> trunk bt
    gemm_mma_kernel<CIN><<<ggrid, 256, SMEM_GEMM>>>(w, bt, fuse_b);
    finalize_kernel<<<COUT, 256>>>(fuse_g, fuse_be);
    applyT_kernel<false, false, true><<<agrid, ablk>>>(nullptr, bt, nullptr);

    for (int i = 0; i < 2; i++) {
        gemm_mma_kernel<COUT><<<ggrid, 256, SMEM_GEMM>>>(
            w + OFF_W1 + (size_t)i * CC, bt, blk_b1 + (size_t)i * COUT);
        finalize_kernel<<<COUT, 256>>>(blk_g1 + (size_t)i * COUT, blk_be1 + (size_t)i * COUT);
        applyT_kernel<false, false, true><<<agrid, ablk>>>(nullptr, by, nullptr);

        gemm_mma_kernel<COUT><<<ggrid, 256, SMEM_GEMM>>>(
            w + OFF_W2 + (size_t)i * CC, by, blk_b2 + (size_t)i * COUT);
        finalize_kernel<<<COUT, 256>>>(blk_g2 + (size_t)i * COUT, blk_be2 + (size_t)i * COUT);
        if (i == 0)
            applyT_kernel<true, false, true><<<agrid, ablk>>>(bt, bt, nullptr);
        else
            applyT_kernel<true, true, false><<<agrid, ablk>>>(bt, nullptr, out);
    }
}